// round 1
// baseline (speedup 1.0000x reference)
#include <cuda_runtime.h>
#include <cuda_bf16.h>

// DB4 multilevel DWT decomposition, one CTA per row, all 11 levels in SMEM.
//
// Reference semantics (derived from the truncated-matrix structure):
//   level 0 (L=4096): circular 4-tap filter pairs
//   levels 1..10 (L<4096): truncated — wrapped taps are ZERO (not circular)
//   each level: a[k]=y[2k] -> s[k], d[k]=y[2k+1] -> s[L/2+k], recurse on s[0:L/2]

#define ROW_N   4096
#define THREADS 256

__global__ __launch_bounds__(THREADS)
void dwt_db4_kernel(const float* __restrict__ x, float* __restrict__ out)
{
    __shared__ float s[ROW_N];

    const int tid = threadIdx.x;
    const long long row = blockIdx.x;

    // ---- load full row, vectorized ----
    {
        const float4* src = reinterpret_cast<const float4*>(x + row * ROW_N);
        float4* s4 = reinterpret_cast<float4*>(s);
        #pragma unroll
        for (int i = 0; i < ROW_N / 4 / THREADS; ++i)
            s4[tid + i * THREADS] = src[tid + i * THREADS];
    }
    __syncthreads();

    const float c0 =  0.4829629131445341f;
    const float c1 =  0.8365163037378079f;
    const float c2 =  0.2241438680420134f;
    const float c3 = -0.1294095225512604f;

    // ---- level 0: L = 4096, circular wrap ----
    {
        const int L = ROW_N;
        const int half = L >> 1;           // 2048 -> 8 pairs per thread
        float ya[8], yd[8];
        #pragma unroll
        for (int j = 0; j < 8; ++j) {
            int k = tid + j * THREADS;
            float x0 = s[2 * k];
            float x1 = s[2 * k + 1];
            float x2 = s[(2 * k + 2) & (L - 1)];
            float x3 = s[(2 * k + 3) & (L - 1)];
            ya[j] = c0 * x0 + c1 * x1 + c2 * x2 + c3 * x3;
            yd[j] = c3 * x0 - c2 * x1 + c1 * x2 - c0 * x3;
        }
        __syncthreads();
        #pragma unroll
        for (int j = 0; j < 8; ++j) {
            int k = tid + j * THREADS;
            s[k]        = ya[j];
            s[half + k] = yd[j];
        }
        __syncthreads();
    }

    // ---- levels 1..10: L = 2048 .. 4, truncated (no wrap) ----
    for (int L = ROW_N >> 1; L >= 4; L >>= 1) {
        const int half = L >> 1;           // <= 1024 -> <= 4 pairs per thread
        float ya[4], yd[4];
        int cnt = 0;
        for (int k = tid; k < half; k += THREADS, ++cnt) {
            float x0 = s[2 * k];
            float x1 = s[2 * k + 1];
            float x2 = (2 * k + 2 < L) ? s[2 * k + 2] : 0.0f;
            float x3 = (2 * k + 3 < L) ? s[2 * k + 3] : 0.0f;
            ya[cnt] = c0 * x0 + c1 * x1 + c2 * x2 + c3 * x3;
            yd[cnt] = c3 * x0 - c2 * x1 + c1 * x2 - c0 * x3;
        }
        __syncthreads();
        cnt = 0;
        for (int k = tid; k < half; k += THREADS, ++cnt) {
            s[k]        = ya[cnt];
            s[half + k] = yd[cnt];
        }
        __syncthreads();
    }

    // ---- store full row, vectorized ----
    {
        float4* dst = reinterpret_cast<float4*>(out + row * ROW_N);
        const float4* s4 = reinterpret_cast<const float4*>(s);
        #pragma unroll
        for (int i = 0; i < ROW_N / 4 / THREADS; ++i)
            dst[tid + i * THREADS] = s4[tid + i * THREADS];
    }
}

extern "C" void kernel_launch(void* const* d_in, const int* in_sizes, int n_in,
                              void* d_out, int out_size)
{
    const float* x = (const float*)d_in[0];   // input (B, 4096)
    // d_in[1] = W is a deterministic DB4 matrix; taps are hardcoded.
    float* out = (float*)d_out;

    const int B = in_sizes[0] / ROW_N;        // 4096 rows
    dwt_db4_kernel<<<B, THREADS>>>(x, out);
}

// round 2
// speedup vs baseline: 1.1250x; 1.1250x over previous
#include <cuda_runtime.h>
#include <cuda_bf16.h>

// DB4 multilevel DWT, one CTA per row, ping-pong SMEM buffers.
//
// Level 0 (L=4096, circular) computes straight from global float2 loads.
// Each subsequent level L: read a-buffer (float2, conflict-free), write
//   a -> other a-buffer [0, L/2), d -> F[L/2, L)   -- one barrier per level.
// Levels with half<=32 are handled by warp 0 with __syncwarp only.

#define ROW_N   4096
#define T       256

__device__ __forceinline__ float2 f2zero() { return make_float2(0.f, 0.f); }

#define C0  0.4829629131445341f
#define C1  0.8365163037378079f
#define C2  0.2241438680420134f
#define C3 (-0.1294095225512604f)

// One truncated level: HALF output pairs. Reads rbuf[0, 2*HALF) as float2,
// writes a -> abuf[0, HALF), d -> dbuf[0, HALF). Truncation: taps past the
// end are zero (matches the truncated W[:L,:L] structure).
template<int HALF>
__device__ __forceinline__ void dwt_level(const float* __restrict__ rbuf,
                                          float* __restrict__ abuf,
                                          float* __restrict__ dbuf,
                                          int tid)
{
    const float2* f2 = reinterpret_cast<const float2*>(rbuf);
    if (HALF >= T) {
        #pragma unroll
        for (int j = 0; j < HALF / T; ++j) {
            const int k = tid + j * T;
            float2 p = f2[k];
            float2 q = (k + 1 < HALF) ? f2[k + 1] : f2zero();
            abuf[k] = C0 * p.x + C1 * p.y + C2 * q.x + C3 * q.y;
            dbuf[k] = C3 * p.x - C2 * p.y + C1 * q.x - C0 * q.y;
        }
    } else {
        if (tid < HALF) {
            const int k = tid;
            float2 p = f2[k];
            float2 q = (k + 1 < HALF) ? f2[k + 1] : f2zero();
            abuf[k] = C0 * p.x + C1 * p.y + C2 * q.x + C3 * q.y;
            dbuf[k] = C3 * p.x - C2 * p.y + C1 * q.x - C0 * q.y;
        }
    }
}

__global__ __launch_bounds__(T)
void dwt_db4_kernel(const float* __restrict__ x, float* __restrict__ out)
{
    __shared__ float F[ROW_N];    // final result assembly (d-halves + last a)
    __shared__ float A[2048];     // a-buffer ping
    __shared__ float Bb[1024];    // a-buffer pong

    const int tid = threadIdx.x;
    const long long row = blockIdx.x;

    // ---- level 0: L=4096, circular, straight from global ----
    {
        const float2* g2 = reinterpret_cast<const float2*>(x + row * ROW_N);
        #pragma unroll
        for (int j = 0; j < 2048 / T; ++j) {
            const int k = tid + j * T;
            float2 p = g2[k];
            float2 q = g2[(k + 1) & 2047];     // circular wrap
            A[k]        = C0 * p.x + C1 * p.y + C2 * q.x + C3 * q.y;
            F[2048 + k] = C3 * p.x - C2 * p.y + C1 * q.x - C0 * q.y;
        }
    }
    __syncthreads();

    // ---- truncated levels, multi-warp part ----
    dwt_level<1024>(A,  Bb, F + 1024, tid); __syncthreads();
    dwt_level< 512>(Bb, A,  F +  512, tid); __syncthreads();
    dwt_level< 256>(A,  Bb, F +  256, tid); __syncthreads();
    dwt_level< 128>(Bb, A,  F +  128, tid); __syncthreads();
    dwt_level<  64>(A,  Bb, F +   64, tid); __syncthreads();

    // ---- tail levels: warp 0 only ----
    if (tid < 32) {
        dwt_level<32>(Bb, A,  F + 32, tid); __syncwarp();
        dwt_level<16>(A,  Bb, F + 16, tid); __syncwarp();
        dwt_level< 8>(Bb, A,  F +  8, tid); __syncwarp();
        dwt_level< 4>(A,  Bb, F +  4, tid); __syncwarp();
        dwt_level< 2>(Bb, F,  F +  2, tid);
    }
    __syncthreads();

    // ---- store final row, vectorized ----
    {
        float4* dst = reinterpret_cast<float4*>(out + row * ROW_N);
        const float4* s4 = reinterpret_cast<const float4*>(F);
        #pragma unroll
        for (int i = 0; i < ROW_N / 4 / T; ++i)
            dst[tid + i * T] = s4[tid + i * T];
    }
}

extern "C" void kernel_launch(void* const* d_in, const int* in_sizes, int n_in,
                              void* d_out, int out_size)
{
    const float* x = (const float*)d_in[0];   // (B, 4096) float32
    // d_in[1] = W is the deterministic DB4 matrix; taps are hardcoded.
    float* out = (float*)d_out;

    const int B = in_sizes[0] / ROW_N;        // 4096 rows
    dwt_db4_kernel<<<B, T>>>(x, out);
}

// round 4
// speedup vs baseline: 1.3061x; 1.1610x over previous
#include <cuda_runtime.h>
#include <cuda_bf16.h>

// DB4 multilevel DWT, one CTA per row. d-halves are streamed DIRECTLY to
// global at each level (each is a final contiguous output chunk); only the
// a-coefficients ping-pong through two small SMEM buffers (12 KB total).
// Each work item computes 2 output pairs from one float4 + one float2 load.

#define ROW_N 4096
#define T     256

#define C0  0.4829629131445341f
#define C1  0.8365163037378079f
#define C2  0.2241438680420134f
#define C3 (-0.1294095225512604f)

// One truncated level with HALF output pairs (HALF >= 2, even).
// Reads rbuf[0, 2*HALF); writes a -> abuf[0, HALF), d -> dbuf[0, HALF).
// Work item t computes outputs 2t and 2t+1; taps past the end are zero.
template<int HALF>
__device__ __forceinline__ void dwt_level(const float* __restrict__ rbuf,
                                          float* __restrict__ abuf,
                                          float* __restrict__ dbuf,
                                          int tid)
{
    constexpr int W = HALF / 2;
    const float4* f4 = reinterpret_cast<const float4*>(rbuf);
    const float2* f2 = reinterpret_cast<const float2*>(rbuf);
    float2* a2 = reinterpret_cast<float2*>(abuf);
    float2* d2 = reinterpret_cast<float2*>(dbuf);

    #pragma unroll
    for (int j = 0; j < (W + T - 1) / T; ++j) {
        const int t = tid + j * T;
        if (W >= T || t < W) {
            float4 v = f4[t];                                  // pairs 2t, 2t+1
            float2 q = (t < W - 1) ? f2[2 * t + 2]
                                   : make_float2(0.f, 0.f);    // truncation
            float a0 = C0 * v.x + C1 * v.y + C2 * v.z + C3 * v.w;
            float d0 = C3 * v.x - C2 * v.y + C1 * v.z - C0 * v.w;
            float a1 = C0 * v.z + C1 * v.w + C2 * q.x + C3 * q.y;
            float d1 = C3 * v.z - C2 * v.w + C1 * q.x - C0 * q.y;
            a2[t] = make_float2(a0, a1);
            d2[t] = make_float2(d0, d1);
        }
    }
}

__global__ __launch_bounds__(T)
void dwt_db4_kernel(const float* __restrict__ x, float* __restrict__ out)
{
    __shared__ float A[2048];     // a-buffer ping
    __shared__ float Bb[1024];    // a-buffer pong

    const int tid = threadIdx.x;
    const long long row = blockIdx.x;
    const float* xr = x + row * ROW_N;
    float* o = out + row * ROW_N;

    // ---- level 0: L=4096, circular, straight from global ----
    {
        const float4* g4 = reinterpret_cast<const float4*>(xr);
        const float2* g2 = reinterpret_cast<const float2*>(xr);
        float2* a2 = reinterpret_cast<float2*>(A);
        float2* d2 = reinterpret_cast<float2*>(o + 2048);
        #pragma unroll
        for (int j = 0; j < 1024 / T; ++j) {
            const int t = tid + j * T;
            float4 v = g4[t];
            float2 q = g2[(2 * t + 2) & 2047];                 // circular wrap
            float a0 = C0 * v.x + C1 * v.y + C2 * v.z + C3 * v.w;
            float d0 = C3 * v.x - C2 * v.y + C1 * v.z - C0 * v.w;
            float a1 = C0 * v.z + C1 * v.w + C2 * q.x + C3 * q.y;
            float d1 = C3 * v.z - C2 * v.w + C1 * q.x - C0 * q.y;
            a2[t] = make_float2(a0, a1);
            d2[t] = make_float2(d0, d1);
        }
    }
    __syncthreads();

    // ---- truncated levels, multi-warp part ----
    dwt_level<1024>(A,  Bb, o + 1024, tid); __syncthreads();
    dwt_level< 512>(Bb, A,  o +  512, tid); __syncthreads();
    dwt_level< 256>(A,  Bb, o +  256, tid); __syncthreads();
    dwt_level< 128>(Bb, A,  o +  128, tid); __syncthreads();

    // ---- tail levels: warp 0 only (W <= 32 work items) ----
    if (tid < 32) {
        dwt_level<64>(A,  Bb, o + 64, tid); __syncwarp();
        dwt_level<32>(Bb, A,  o + 32, tid); __syncwarp();
        dwt_level<16>(A,  Bb, o + 16, tid); __syncwarp();
        dwt_level< 8>(Bb, A,  o +  8, tid); __syncwarp();
        dwt_level< 4>(A,  Bb, o +  4, tid); __syncwarp();
        dwt_level< 2>(Bb, o,  o +  2, tid);   // final a -> out[0:2], d -> out[2:4]
    }
}

extern "C" void kernel_launch(void* const* d_in, const int* in_sizes, int n_in,
                              void* d_out, int out_size)
{
    const float* x = (const float*)d_in[0];   // (B, 4096) float32
    // d_in[1] = W is the deterministic DB4 matrix; taps are hardcoded.
    float* out = (float*)d_out;

    const int B = in_sizes[0] / ROW_N;        // 4096 rows
    dwt_db4_kernel<<<B, T>>>(x, out);
}

// round 5
// speedup vs baseline: 1.3682x; 1.0475x over previous
#include <cuda_runtime.h>
#include <cuda_bf16.h>

// DB4 multilevel DWT, one CTA per row. d-halves are streamed DIRECTLY to
// global at each level (each is a final contiguous output chunk); only the
// a-coefficients ping-pong through two small SMEM buffers (12 KB total).
// Each work item computes 2 output pairs from one float4 + one float2 load.

#define ROW_N 4096
#define T     256

#define C0  0.4829629131445341f
#define C1  0.8365163037378079f
#define C2  0.2241438680420134f
#define C3 (-0.1294095225512604f)

// One truncated level with HALF output pairs (HALF >= 2, even).
// Reads rbuf[0, 2*HALF); writes a -> abuf[0, HALF), d -> dbuf[0, HALF).
// Work item t computes outputs 2t and 2t+1; taps past the end are zero.
template<int HALF>
__device__ __forceinline__ void dwt_level(const float* __restrict__ rbuf,
                                          float* __restrict__ abuf,
                                          float* __restrict__ dbuf,
                                          int tid)
{
    constexpr int W = HALF / 2;
    const float4* f4 = reinterpret_cast<const float4*>(rbuf);
    const float2* f2 = reinterpret_cast<const float2*>(rbuf);
    float2* a2 = reinterpret_cast<float2*>(abuf);
    float2* d2 = reinterpret_cast<float2*>(dbuf);

    #pragma unroll
    for (int j = 0; j < (W + T - 1) / T; ++j) {
        const int t = tid + j * T;
        if (W >= T || t < W) {
            float4 v = f4[t];                                  // pairs 2t, 2t+1
            float2 q = (t < W - 1) ? f2[2 * t + 2]
                                   : make_float2(0.f, 0.f);    // truncation
            float a0 = C0 * v.x + C1 * v.y + C2 * v.z + C3 * v.w;
            float d0 = C3 * v.x - C2 * v.y + C1 * v.z - C0 * v.w;
            float a1 = C0 * v.z + C1 * v.w + C2 * q.x + C3 * q.y;
            float d1 = C3 * v.z - C2 * v.w + C1 * q.x - C0 * q.y;
            a2[t] = make_float2(a0, a1);
            d2[t] = make_float2(d0, d1);
        }
    }
}

__global__ __launch_bounds__(T)
void dwt_db4_kernel(const float* __restrict__ x, float* __restrict__ out)
{
    __shared__ float A[2048];     // a-buffer ping
    __shared__ float Bb[1024];    // a-buffer pong

    const int tid = threadIdx.x;
    const long long row = blockIdx.x;
    const float* xr = x + row * ROW_N;
    float* o = out + row * ROW_N;

    // ---- level 0: L=4096, circular, straight from global ----
    {
        const float4* g4 = reinterpret_cast<const float4*>(xr);
        const float2* g2 = reinterpret_cast<const float2*>(xr);
        float2* a2 = reinterpret_cast<float2*>(A);
        float2* d2 = reinterpret_cast<float2*>(o + 2048);
        #pragma unroll
        for (int j = 0; j < 1024 / T; ++j) {
            const int t = tid + j * T;
            float4 v = g4[t];
            float2 q = g2[(2 * t + 2) & 2047];                 // circular wrap
            float a0 = C0 * v.x + C1 * v.y + C2 * v.z + C3 * v.w;
            float d0 = C3 * v.x - C2 * v.y + C1 * v.z - C0 * v.w;
            float a1 = C0 * v.z + C1 * v.w + C2 * q.x + C3 * q.y;
            float d1 = C3 * v.z - C2 * v.w + C1 * q.x - C0 * q.y;
            a2[t] = make_float2(a0, a1);
            d2[t] = make_float2(d0, d1);
        }
    }
    __syncthreads();

    // ---- truncated levels, multi-warp part ----
    dwt_level<1024>(A,  Bb, o + 1024, tid); __syncthreads();
    dwt_level< 512>(Bb, A,  o +  512, tid); __syncthreads();
    dwt_level< 256>(A,  Bb, o +  256, tid); __syncthreads();
    dwt_level< 128>(Bb, A,  o +  128, tid); __syncthreads();

    // ---- tail levels: warp 0 only (W <= 32 work items) ----
    if (tid < 32) {
        dwt_level<64>(A,  Bb, o + 64, tid); __syncwarp();
        dwt_level<32>(Bb, A,  o + 32, tid); __syncwarp();
        dwt_level<16>(A,  Bb, o + 16, tid); __syncwarp();
        dwt_level< 8>(Bb, A,  o +  8, tid); __syncwarp();
        dwt_level< 4>(A,  Bb, o +  4, tid); __syncwarp();
        dwt_level< 2>(Bb, o,  o +  2, tid);   // final a -> out[0:2], d -> out[2:4]
    }
}

extern "C" void kernel_launch(void* const* d_in, const int* in_sizes, int n_in,
                              void* d_out, int out_size)
{
    const float* x = (const float*)d_in[0];   // (B, 4096) float32
    // d_in[1] = W is the deterministic DB4 matrix; taps are hardcoded.
    float* out = (float*)d_out;

    const int B = in_sizes[0] / ROW_N;        // 4096 rows
    dwt_db4_kernel<<<B, T>>>(x, out);
}

// round 8
// speedup vs baseline: 1.3846x; 1.0120x over previous
#include <cuda_runtime.h>
#include <cuda_bf16.h>

// DB4 multilevel DWT, one CTA per row. a-coefficients live in REGISTERS and
// flow between levels via warp shuffles; cross-warp edges use tiny SMEM
// tables. One 4KB SMEM transpose re-blocks after level 1; warp 0 finishes
// levels 4..10 entirely in registers. All d-halves stream directly to global.

#define ROW_N 4096
#define T     256

#define C0  0.4829629131445341f
#define C1  0.8365163037378079f
#define C2  0.2241438680420134f
#define C3 (-0.1294095225512604f)

#define PAIR_A(x0,x1,x2,x3) (C0*(x0) + C1*(x1) + C2*(x2) + C3*(x3))
#define PAIR_D(x0,x1,x2,x3) (C3*(x0) - C2*(x1) + C1*(x2) - C0*(x3))

__global__ __launch_bounds__(T)
void dwt_db4_kernel(const float* __restrict__ x, float* __restrict__ out)
{
    __shared__ float eA[8][4][2];   // level-1 cross-warp edges (warp, group, 2)
    __shared__ float s1[1024];      // a1 transpose buffer
    __shared__ float eB[8][2];      // level-3 cross-warp edges
    __shared__ float a3s[256];      // handoff to warp 0

    const int t = threadIdx.x;
    const int w = t >> 5;
    const int l = t & 31;
    const unsigned FULL = 0xffffffffu;

    const float* xr = x + (long long)blockIdx.x * ROW_N;
    float*       o  = out + (long long)blockIdx.x * ROW_N;
    const float4* g4 = reinterpret_cast<const float4*>(xr);
    const float2* g2 = reinterpret_cast<const float2*>(xr);

    // ---- level 0 (L=4096, circular): thread t, group j owns pair u=t+256j ----
    float a0[4][2];
    #pragma unroll
    for (int j = 0; j < 4; ++j) {
        const int u = t + 256 * j;
        float4 v = g4[u];
        float2 q = g2[(2 * u + 2) & 2047];          // circular wrap
        float A0 = PAIR_A(v.x, v.y, v.z, v.w);
        float D0 = PAIR_D(v.x, v.y, v.z, v.w);
        float A1 = PAIR_A(v.z, v.w, q.x, q.y);
        float D1 = PAIR_D(v.z, v.w, q.x, q.y);
        a0[j][0] = A0; a0[j][1] = A1;
        reinterpret_cast<float2*>(o + 2048)[u] = make_float2(D0, D1);
        if (l == 0) { eA[w][j][0] = A0; eA[w][j][1] = A1; }
    }
    __syncthreads();

    // ---- level 1 (2048->1024): pair m=t+256j needs own 2 + neighbor's 2 ----
    #pragma unroll
    for (int j = 0; j < 4; ++j) {
        float n0 = __shfl_down_sync(FULL, a0[j][0], 1);
        float n1 = __shfl_down_sync(FULL, a0[j][1], 1);
        if (l == 31) {
            if (w < 7)      { n0 = eA[w + 1][j][0]; n1 = eA[w + 1][j][1]; }
            else if (j < 3) { n0 = eA[0][j + 1][0]; n1 = eA[0][j + 1][1]; }
            else            { n0 = 0.f; n1 = 0.f; }            // truncation
        }
        float A = PAIR_A(a0[j][0], a0[j][1], n0, n1);
        float D = PAIR_D(a0[j][0], a0[j][1], n0, n1);
        s1[t + 256 * j]       = A;                  // coalesced STS (transpose)
        o[1024 + t + 256 * j] = D;                  // coalesced STG
    }
    __syncthreads();

    // ---- level 2 (1024->512): thread t holds a1[4t..4t+4), pairs 2t,2t+1 ----
    float a2x, a2y;
    {
        float4 v = reinterpret_cast<const float4*>(s1)[t];   // LDS.128
        float n0 = __shfl_down_sync(FULL, v.x, 1);
        float n1 = __shfl_down_sync(FULL, v.y, 1);
        if (l == 31) {
            if (t < 255) { n0 = s1[4 * t + 4]; n1 = s1[4 * t + 5]; }
            else         { n0 = 0.f; n1 = 0.f; }               // truncation
        }
        float A0 = PAIR_A(v.x, v.y, v.z, v.w);
        float D0 = PAIR_D(v.x, v.y, v.z, v.w);
        float A1 = PAIR_A(v.z, v.w, n0, n1);
        float D1 = PAIR_D(v.z, v.w, n0, n1);
        reinterpret_cast<float2*>(o + 512)[t] = make_float2(D0, D1);
        a2x = A0; a2y = A1;
        if (l == 0) { eB[w][0] = A0; eB[w][1] = A1; }
    }
    __syncthreads();

    // ---- level 3 (512->256): pair t needs own a2 pair + neighbor's ----
    {
        float n0 = __shfl_down_sync(FULL, a2x, 1);
        float n1 = __shfl_down_sync(FULL, a2y, 1);
        if (l == 31) {
            if (w < 7) { n0 = eB[w + 1][0]; n1 = eB[w + 1][1]; }
            else       { n0 = 0.f; n1 = 0.f; }                 // truncation
        }
        o[256 + t] = PAIR_D(a2x, a2y, n0, n1);
        a3s[t]     = PAIR_A(a2x, a2y, n0, n1);
    }
    __syncthreads();

    // ---- warp 0: levels 4..10 on 256 values, all in registers ----
    if (w == 0) {
        float4 u0 = reinterpret_cast<const float4*>(a3s)[2 * l];
        float4 u1 = reinterpret_cast<const float4*>(a3s)[2 * l + 1];
        // lane l holds a3[8l..8l+8)
        // level 4 (256->128): pairs 4l..4l+3
        float n0 = __shfl_down_sync(FULL, u0.x, 1);
        float n1 = __shfl_down_sync(FULL, u0.y, 1);
        if (l == 31) { n0 = 0.f; n1 = 0.f; }
        float a4_0 = PAIR_A(u0.x, u0.y, u0.z, u0.w);
        float a4_1 = PAIR_A(u0.z, u0.w, u1.x, u1.y);
        float a4_2 = PAIR_A(u1.x, u1.y, u1.z, u1.w);
        float a4_3 = PAIR_A(u1.z, u1.w, n0,  n1);
        float4 d4;
        d4.x = PAIR_D(u0.x, u0.y, u0.z, u0.w);
        d4.y = PAIR_D(u0.z, u0.w, u1.x, u1.y);
        d4.z = PAIR_D(u1.x, u1.y, u1.z, u1.w);
        d4.w = PAIR_D(u1.z, u1.w, n0,  n1);
        reinterpret_cast<float4*>(o + 128)[l] = d4;

        // level 5 (128->64): pairs 2l,2l+1
        n0 = __shfl_down_sync(FULL, a4_0, 1);
        n1 = __shfl_down_sync(FULL, a4_1, 1);
        if (l == 31) { n0 = 0.f; n1 = 0.f; }
        float a5_0 = PAIR_A(a4_0, a4_1, a4_2, a4_3);
        float a5_1 = PAIR_A(a4_2, a4_3, n0,  n1);
        float2 d5;
        d5.x = PAIR_D(a4_0, a4_1, a4_2, a4_3);
        d5.y = PAIR_D(a4_2, a4_3, n0,  n1);
        reinterpret_cast<float2*>(o + 64)[l] = d5;

        // level 6 (64->32): pair l
        n0 = __shfl_down_sync(FULL, a5_0, 1);
        n1 = __shfl_down_sync(FULL, a5_1, 1);
        if (l == 31) { n0 = 0.f; n1 = 0.f; }
        float a6 = PAIR_A(a5_0, a5_1, n0, n1);
        o[32 + l] = PAIR_D(a5_0, a5_1, n0, n1);

        // levels 7..10: 1 value/lane, gather via indexed shuffle, zero past end
        float a = a6;
        #pragma unroll
        for (int Lprev = 32; Lprev >= 4; Lprev >>= 1) {
            float p0 = __shfl_sync(FULL, a, (2 * l)     & 31);
            float p1 = __shfl_sync(FULL, a, (2 * l + 1) & 31);
            float p2 = __shfl_sync(FULL, a, (2 * l + 2) & 31);
            float p3 = __shfl_sync(FULL, a, (2 * l + 3) & 31);
            if (2 * l + 2 >= Lprev) p2 = 0.f;
            if (2 * l + 3 >= Lprev) p3 = 0.f;
            float an = PAIR_A(p0, p1, p2, p3);
            float dn = PAIR_D(p0, p1, p2, p3);
            const int half = Lprev >> 1;
            if (l < half) {
                if (Lprev > 4) o[half + l] = dn;
                else { o[l] = an; o[2 + l] = dn; }   // final level: a too
            }
            a = an;
        }
    }
}

extern "C" void kernel_launch(void* const* d_in, const int* in_sizes, int n_in,
                              void* d_out, int out_size)
{
    const float* x = (const float*)d_in[0];   // (B, 4096) float32
    // d_in[1] = W is the deterministic DB4 matrix; taps are hardcoded.
    float* out = (float*)d_out;

    const int B = in_sizes[0] / ROW_N;        // 4096 rows
    dwt_db4_kernel<<<B, T>>>(x, out);
}

// round 9
// speedup vs baseline: 1.4807x; 1.0694x over previous
#include <cuda_runtime.h>
#include <cuda_bf16.h>

// DB4 multilevel DWT, one CTA per row. Input is loaded EXACTLY ONCE (float4);
// all neighbor taps at every level come from warp shuffles + tiny SMEM edge
// tables. a-coefficients stay in registers; d-halves stream straight to
// global. Warp 0 finishes levels 4..10 entirely in registers.

#define ROW_N 4096
#define T     256

#define C0  0.4829629131445341f
#define C1  0.8365163037378079f
#define C2  0.2241438680420134f
#define C3 (-0.1294095225512604f)

#define PAIR_A(x0,x1,x2,x3) (C0*(x0) + C1*(x1) + C2*(x2) + C3*(x3))
#define PAIR_D(x0,x1,x2,x3) (C3*(x0) - C2*(x1) + C1*(x2) - C0*(x3))

__global__ __launch_bounds__(T)
void dwt_db4_kernel(const float* __restrict__ x, float* __restrict__ out)
{
    __shared__ float eV[8][4][2];   // level-0 edges: lane-0 (v.x,v.y) per warp/group
    __shared__ float eA[8][4][2];   // level-1 edges
    __shared__ float s1[1024];      // a1 transpose buffer
    __shared__ float eB[8][2];      // level-3 edges
    __shared__ float a3s[256];      // handoff to warp 0

    const int t = threadIdx.x;
    const int w = t >> 5;
    const int l = t & 31;
    const unsigned FULL = 0xffffffffu;

    const float* xr = x + (long long)blockIdx.x * ROW_N;
    float*       o  = out + (long long)blockIdx.x * ROW_N;
    const float4* g4 = reinterpret_cast<const float4*>(xr);

    // ---- load: thread t, group j owns float4 u = t+256j (input read ONCE) ----
    float4 v[4];
    #pragma unroll
    for (int j = 0; j < 4; ++j) v[j] = g4[t + 256 * j];
    if (l == 0) {
        #pragma unroll
        for (int j = 0; j < 4; ++j) { eV[w][j][0] = v[j].x; eV[w][j][1] = v[j].y; }
    }
    __syncthreads();

    // ---- level 0 (L=4096, circular): neighbor (x[4u+4],x[4u+5]) via shuffle ----
    float a0[4][2];
    #pragma unroll
    for (int j = 0; j < 4; ++j) {
        const int u = t + 256 * j;
        float qx = __shfl_down_sync(FULL, v[j].x, 1);
        float qy = __shfl_down_sync(FULL, v[j].y, 1);
        if (l == 31) {
            if (w < 7)      { qx = eV[w + 1][j][0]; qy = eV[w + 1][j][1]; }
            else if (j < 3) { qx = eV[0][j + 1][0]; qy = eV[0][j + 1][1]; }
            else            { qx = eV[0][0][0];     qy = eV[0][0][1]; }  // circular wrap
        }
        float A0 = PAIR_A(v[j].x, v[j].y, v[j].z, v[j].w);
        float D0 = PAIR_D(v[j].x, v[j].y, v[j].z, v[j].w);
        float A1 = PAIR_A(v[j].z, v[j].w, qx, qy);
        float D1 = PAIR_D(v[j].z, v[j].w, qx, qy);
        a0[j][0] = A0; a0[j][1] = A1;
        reinterpret_cast<float2*>(o + 2048)[u] = make_float2(D0, D1);
        if (l == 0) { eA[w][j][0] = A0; eA[w][j][1] = A1; }
    }
    __syncthreads();

    // ---- level 1 (2048->1024): pair m=t+256j needs own 2 + neighbor's 2 ----
    #pragma unroll
    for (int j = 0; j < 4; ++j) {
        float n0 = __shfl_down_sync(FULL, a0[j][0], 1);
        float n1 = __shfl_down_sync(FULL, a0[j][1], 1);
        if (l == 31) {
            if (w < 7)      { n0 = eA[w + 1][j][0]; n1 = eA[w + 1][j][1]; }
            else if (j < 3) { n0 = eA[0][j + 1][0]; n1 = eA[0][j + 1][1]; }
            else            { n0 = 0.f; n1 = 0.f; }            // truncation
        }
        float A = PAIR_A(a0[j][0], a0[j][1], n0, n1);
        float D = PAIR_D(a0[j][0], a0[j][1], n0, n1);
        s1[t + 256 * j]       = A;                  // coalesced STS (transpose)
        o[1024 + t + 256 * j] = D;                  // coalesced STG
    }
    __syncthreads();

    // ---- level 2 (1024->512): thread t holds a1[4t..4t+4), pairs 2t,2t+1 ----
    float a2x, a2y;
    {
        float4 u4 = reinterpret_cast<const float4*>(s1)[t];   // LDS.128
        float n0 = __shfl_down_sync(FULL, u4.x, 1);
        float n1 = __shfl_down_sync(FULL, u4.y, 1);
        if (l == 31) {
            if (t < 255) { n0 = s1[4 * t + 4]; n1 = s1[4 * t + 5]; }
            else         { n0 = 0.f; n1 = 0.f; }               // truncation
        }
        float A0 = PAIR_A(u4.x, u4.y, u4.z, u4.w);
        float D0 = PAIR_D(u4.x, u4.y, u4.z, u4.w);
        float A1 = PAIR_A(u4.z, u4.w, n0, n1);
        float D1 = PAIR_D(u4.z, u4.w, n0, n1);
        reinterpret_cast<float2*>(o + 512)[t] = make_float2(D0, D1);
        a2x = A0; a2y = A1;
        if (l == 0) { eB[w][0] = A0; eB[w][1] = A1; }
    }
    __syncthreads();

    // ---- level 3 (512->256): pair t needs own a2 pair + neighbor's ----
    {
        float n0 = __shfl_down_sync(FULL, a2x, 1);
        float n1 = __shfl_down_sync(FULL, a2y, 1);
        if (l == 31) {
            if (w < 7) { n0 = eB[w + 1][0]; n1 = eB[w + 1][1]; }
            else       { n0 = 0.f; n1 = 0.f; }                 // truncation
        }
        o[256 + t] = PAIR_D(a2x, a2y, n0, n1);
        a3s[t]     = PAIR_A(a2x, a2y, n0, n1);
    }
    __syncthreads();

    // ---- warp 0: levels 4..10 on 256 values, all in registers ----
    if (w == 0) {
        float4 u0 = reinterpret_cast<const float4*>(a3s)[2 * l];
        float4 u1 = reinterpret_cast<const float4*>(a3s)[2 * l + 1];
        // lane l holds a3[8l..8l+8)
        // level 4 (256->128): pairs 4l..4l+3
        float n0 = __shfl_down_sync(FULL, u0.x, 1);
        float n1 = __shfl_down_sync(FULL, u0.y, 1);
        if (l == 31) { n0 = 0.f; n1 = 0.f; }
        float a4_0 = PAIR_A(u0.x, u0.y, u0.z, u0.w);
        float a4_1 = PAIR_A(u0.z, u0.w, u1.x, u1.y);
        float a4_2 = PAIR_A(u1.x, u1.y, u1.z, u1.w);
        float a4_3 = PAIR_A(u1.z, u1.w, n0,  n1);
        float4 d4;
        d4.x = PAIR_D(u0.x, u0.y, u0.z, u0.w);
        d4.y = PAIR_D(u0.z, u0.w, u1.x, u1.y);
        d4.z = PAIR_D(u1.x, u1.y, u1.z, u1.w);
        d4.w = PAIR_D(u1.z, u1.w, n0,  n1);
        reinterpret_cast<float4*>(o + 128)[l] = d4;

        // level 5 (128->64): pairs 2l,2l+1
        n0 = __shfl_down_sync(FULL, a4_0, 1);
        n1 = __shfl_down_sync(FULL, a4_1, 1);
        if (l == 31) { n0 = 0.f; n1 = 0.f; }
        float a5_0 = PAIR_A(a4_0, a4_1, a4_2, a4_3);
        float a5_1 = PAIR_A(a4_2, a4_3, n0,  n1);
        float2 d5;
        d5.x = PAIR_D(a4_0, a4_1, a4_2, a4_3);
        d5.y = PAIR_D(a4_2, a4_3, n0,  n1);
        reinterpret_cast<float2*>(o + 64)[l] = d5;

        // level 6 (64->32): pair l
        n0 = __shfl_down_sync(FULL, a5_0, 1);
        n1 = __shfl_down_sync(FULL, a5_1, 1);
        if (l == 31) { n0 = 0.f; n1 = 0.f; }
        float a6 = PAIR_A(a5_0, a5_1, n0, n1);
        o[32 + l] = PAIR_D(a5_0, a5_1, n0, n1);

        // levels 7..10: 1 value/lane, gather via indexed shuffle, zero past end
        float a = a6;
        #pragma unroll
        for (int Lprev = 32; Lprev >= 4; Lprev >>= 1) {
            float p0 = __shfl_sync(FULL, a, (2 * l)     & 31);
            float p1 = __shfl_sync(FULL, a, (2 * l + 1) & 31);
            float p2 = __shfl_sync(FULL, a, (2 * l + 2) & 31);
            float p3 = __shfl_sync(FULL, a, (2 * l + 3) & 31);
            if (2 * l + 2 >= Lprev) p2 = 0.f;
            if (2 * l + 3 >= Lprev) p3 = 0.f;
            float an = PAIR_A(p0, p1, p2, p3);
            float dn = PAIR_D(p0, p1, p2, p3);
            const int half = Lprev >> 1;
            if (l < half) {
                if (Lprev > 4) o[half + l] = dn;
                else { o[l] = an; o[2 + l] = dn; }   // final level: a too
            }
            a = an;
        }
    }
}

extern "C" void kernel_launch(void* const* d_in, const int* in_sizes, int n_in,
                              void* d_out, int out_size)
{
    const float* x = (const float*)d_in[0];   // (B, 4096) float32
    // d_in[1] = W is the deterministic DB4 matrix; taps are hardcoded.
    float* out = (float*)d_out;

    const int B = in_sizes[0] / ROW_N;        // 4096 rows
    dwt_db4_kernel<<<B, T>>>(x, out);
}